// round 6
// baseline (speedup 1.0000x reference)
#include <cuda_runtime.h>
#include <cstdint>

#define NUM_CLASSES 10
#define NBATCH 4
#define PER_BATCH 4096000        // 160^3 elements per batch
#define PB4 (PER_BATCH / 4)      // 1,024,000 int4 per batch
#define TPB 256
#define NWARP (TPB / 32)
#define GRIDX 74                 // blocks per batch; 74*4 = 296 = 148 SMs * 2 blocks
#define NBLOCKS (GRIDX * NBATCH)
#define CHUNK 13838              // ceil(PB4 / GRIDX) int4 per block (contiguous)
#define SI4 512                  // int4 per input per pipeline stage (8 KB)
#define DEPTH 3                  // ring depth: 3 * 16 KB pair = 48 KB in flight per block
#define ROWS 25                  // 100 keys -> 25 words of 4 byte-counters per lane

__device__ int g_hist[NBATCH * 100];   // pair histogram H[n][p*10 + t]; reset by last block
__device__ int g_done = 0;             // arrival ticket; reset by last block

// ---- mbarrier / TMA-bulk primitives ----
__device__ __forceinline__ uint32_t smem_u32(const void* p) {
    return (uint32_t)__cvta_generic_to_shared(p);
}
__device__ __forceinline__ void mbar_init(uint32_t a, uint32_t cnt) {
    asm volatile("mbarrier.init.shared.b64 [%0], %1;" :: "r"(a), "r"(cnt) : "memory");
}
__device__ __forceinline__ void mbar_arrive(uint32_t a) {
    asm volatile("mbarrier.arrive.shared.b64 _, [%0];" :: "r"(a) : "memory");
}
__device__ __forceinline__ void mbar_expect_tx(uint32_t a, uint32_t bytes) {
    asm volatile("mbarrier.arrive.expect_tx.shared.b64 _, [%0], %1;" :: "r"(a), "r"(bytes) : "memory");
}
__device__ __forceinline__ void mbar_wait(uint32_t a, uint32_t parity) {
    asm volatile(
        "{\n\t.reg .pred P1;\n\t"
        "WAIT_LOOP_%=:\n\t"
        "mbarrier.try_wait.parity.acquire.cta.shared::cta.b64 P1, [%0], %1, 0x989680;\n\t"
        "@P1 bra.uni WAIT_DONE_%=;\n\t"
        "bra.uni WAIT_LOOP_%=;\n\t"
        "WAIT_DONE_%=:\n\t}"
        :: "r"(a), "r"(parity) : "memory");
}
__device__ __forceinline__ void bulk_g2s(uint32_t dst, const void* src, uint32_t bytes, uint32_t mbar) {
    asm volatile("cp.async.bulk.shared::cta.global.mbarrier::complete_tx::bytes [%0], [%1], %2, [%3];"
        :: "r"(dst), "l"(src), "r"(bytes), "r"(mbar) : "memory");
}

// Conflict-free per-thread byte histogram:
// counter k of (warp w, lane l) at byte  w*3200 + (k>>2)*128 + l*4 + (k&3)  -> bank = l always.
#define INC4(a, b)                                              \
    do {                                                        \
        int k0 = (a).x * 10 + (b).x;  my[((k0 & 124) << 5) + (k0 & 3)]++; \
        int k1 = (a).y * 10 + (b).y;  my[((k1 & 124) << 5) + (k1 & 3)]++; \
        int k2 = (a).z * 10 + (b).z;  my[((k2 & 124) << 5) + (k2 & 3)]++; \
        int k3 = (a).w * 10 + (b).w;  my[((k3 & 124) << 5) + (k3 & 3)]++; \
    } while (0)

#define DSMEM_BYTES (2 * DEPTH * SI4 * 16 + NWARP * ROWS * 128)   // 49152 + 25600 = 74752

extern __shared__ __align__(128) unsigned char dsmem[];

__global__ __launch_bounds__(TPB) void dice_fused_kernel(const int4* __restrict__ yp,
                                                         const int4* __restrict__ yt,
                                                         float* __restrict__ out) {
    int4* ring_p = (int4*)dsmem;                       // [DEPTH][SI4]
    int4* ring_t = (int4*)dsmem + DEPTH * SI4;         // [DEPTH][SI4]
    unsigned char* h8 = dsmem + 2 * DEPTH * SI4 * 16;  // [NWARP*ROWS*128]

    __shared__ unsigned long long mbar_full[DEPTH], mbar_empty[DEPTH];
    __shared__ unsigned int wsum[NWARP][ROWS][2];
    __shared__ float s_pred[NBATCH * 10];
    __shared__ float s_true[NBATCH * 10];
    __shared__ float s_int[NBATCH * 10];
    __shared__ int s_last;

    const int tid  = threadIdx.x;
    const int lane = tid & 31;
    const int w    = tid >> 5;
    unsigned char* my = h8 + (w * ROWS * 128 + lane * 4);

    // zero private counters (thread-private: no pre-sync needed)
    #pragma unroll
    for (int r = 0; r < ROWS; r++)
        *reinterpret_cast<unsigned int*>(my + r * 128) = 0u;

    const int batch = blockIdx.y;
    const int base  = blockIdx.x * CHUNK;
    const int count = min(CHUNK, PB4 - base);           // int4 per input in this block's chunk
    const int4* __restrict__ p = yp + (size_t)batch * PB4 + base;
    const int4* __restrict__ t = yt + (size_t)batch * PB4 + base;
    const int nstages = (count + SI4 - 1) / SI4;

    if (tid == 0) {
        #pragma unroll
        for (int s = 0; s < DEPTH; s++) {
            mbar_init(smem_u32(&mbar_full[s]), 1);
            mbar_init(smem_u32(&mbar_empty[s]), TPB);
        }
    }
    __syncthreads();

    // prime the pipeline
    if (tid == 0) {
        int prime = nstages < DEPTH ? nstages : DEPTH;
        for (int s = 0; s < prime; s++) {
            int sc = min(SI4, count - s * SI4);
            uint32_t fb = smem_u32(&mbar_full[s]);
            mbar_expect_tx(fb, (uint32_t)(2 * sc * 16));
            bulk_g2s(smem_u32(ring_p + s * SI4), p + s * SI4, sc * 16, fb);
            bulk_g2s(smem_u32(ring_t + s * SI4), t + s * SI4, sc * 16, fb);
        }
    }

    int slot = 0, phase = 0;
    for (int s = 0; s < nstages; s++) {
        mbar_wait(smem_u32(&mbar_full[slot]), phase);

        const int sbase = s * SI4;
        const int scnt  = min(SI4, count - sbase);
        const int roff  = slot * SI4;
        if (scnt == SI4) {
            // full stage: 2 int4 per thread per input, loads batched for MLP
            int4 a0 = ring_p[roff + tid];
            int4 b0 = ring_t[roff + tid];
            int4 a1 = ring_p[roff + tid + TPB];
            int4 b1 = ring_t[roff + tid + TPB];
            INC4(a0, b0);
            INC4(a1, b1);
        } else {
            for (int j = tid; j < scnt; j += TPB) {
                int4 a = ring_p[roff + j];
                int4 b = ring_t[roff + j];
                INC4(a, b);
            }
        }
        mbar_arrive(smem_u32(&mbar_empty[slot]));   // release: reads done, slot reusable

        if (tid == 0) {
            int ns = s + DEPTH;
            if (ns < nstages) {
                mbar_wait(smem_u32(&mbar_empty[slot]), phase);   // backpressure
                int sc = min(SI4, count - ns * SI4);
                uint32_t fb = smem_u32(&mbar_full[slot]);
                mbar_expect_tx(fb, (uint32_t)(2 * sc * 16));
                bulk_g2s(smem_u32(ring_p + roff), p + ns * SI4, sc * 16, fb);
                bulk_g2s(smem_u32(ring_t + roff), t + ns * SI4, sc * 16, fb);
            }
        }
        if (++slot == DEPTH) { slot = 0; phase ^= 1; }
    }
    // max per-thread elements: <= 2 int4 * 28 stages * 4 = 224 <= 255: no byte overflow

    // Flush: byte-split each word (keys 4r..4r+3) into 16-bit fields, warp-reduce.
    #pragma unroll
    for (int r = 0; r < ROWS; r++) {
        unsigned int word = *reinterpret_cast<unsigned int*>(my + r * 128);
        unsigned int e0 = word & 0x00FF00FFu;          // keys 4r+0 (lo16), 4r+2 (hi16)
        unsigned int e1 = (word >> 8) & 0x00FF00FFu;   // keys 4r+1 (lo16), 4r+3 (hi16)
        unsigned int s0 = __reduce_add_sync(0xFFFFFFFFu, e0);  // <= 32*224 per field: no carry
        unsigned int s1 = __reduce_add_sync(0xFFFFFFFFu, e1);
        if (lane == 0) { wsum[w][r][0] = s0; wsum[w][r][1] = s1; }
    }
    __syncthreads();

    if (tid < 100) {
        int r = tid >> 2, b = tid & 3;
        int sh = (b >> 1) * 16, h = b & 1;
        unsigned int sum = 0;
        #pragma unroll
        for (int ww = 0; ww < NWARP; ww++)
            sum += (wsum[ww][r][h] >> sh) & 0xFFFFu;
        atomicAdd(&g_hist[batch * 100 + tid], (int)sum);
    }
    __syncthreads();

    // ---- last-block-done finalize ----
    if (tid == 0) {
        __threadfence();
        s_last = (atomicAdd(&g_done, 1) == NBLOCKS - 1);
        if (s_last) __threadfence();
    }
    __syncthreads();
    if (!s_last) return;

    if (tid < NBATCH * 10) {
        int n = tid / 10, c = tid % 10;
        int cp = 0, ct = 0;
        #pragma unroll
        for (int k = 0; k < 10; k++) {
            cp += g_hist[n * 100 + c * 10 + k];   // c_pred[n][c]
            ct += g_hist[n * 100 + k * 10 + c];   // c_true[n][c]
        }
        s_pred[tid] = (float)cp;
        s_true[tid] = (float)ct;
        s_int[tid]  = (float)g_hist[n * 100 + c * 10 + c];
    }
    __syncthreads();

    // reset globals for next graph replay
    for (int j = tid; j < NBATCH * 100; j += TPB) g_hist[j] = 0;
    if (tid == 0) g_done = 0;

    if (tid == 0) {
        float loss = 1.0f;
        for (int n = 0; n < NBATCH; n++) {
            float tsum = 0.0f;
            for (int c = 1; c < NUM_CLASSES; c++) tsum += s_true[n * 10 + c];
            for (int c = 1; c < NUM_CLASSES; c++) {
                float cp = s_pred[n * 10 + c];
                float ct = s_true[n * 10 + c];
                float denom = cp + ct;
                if (denom > 0.0f) {
                    float dice = 2.0f * s_int[n * 10 + c] / denom;
                    float wgt = ct / tsum / (float)NBATCH;
                    loss -= wgt * dice;
                }
            }
        }
        out[0] = loss;
    }
}

extern "C" void kernel_launch(void* const* d_in, const int* in_sizes, int n_in,
                              void* d_out, int out_size) {
    const int4* yp = (const int4*)d_in[0];
    const int4* yt = (const int4*)d_in[1];

    cudaFuncSetAttribute(dice_fused_kernel,
                         cudaFuncAttributeMaxDynamicSharedMemorySize, DSMEM_BYTES);
    dim3 grid(GRIDX, NBATCH);
    dice_fused_kernel<<<grid, TPB, DSMEM_BYTES>>>(yp, yt, (float*)d_out);
}